// round 1
// baseline (speedup 1.0000x reference)
#include <cuda_runtime.h>
#include <math.h>

#define NPTS 8192
#define GRP  1024
#define NGRP 8
#define KNN_TOT 360
#define MPAIR (NPTS * 20)
#define EPSV 1e-5

// ---------------- scratch (static device memory; no allocation) ----------------
struct Scratch {
    int    idx[NPTS * KNN_TOT];      // sorted kNN indices (global ids)
    float  A[NPTS * 64];             // Wn @ x   (point-major [n][o])
    float  B[NPTS * 64];             // (Wc-Wn) @ x
    float  z[NPTS * 64];             // max_k y2 (pre-norm)
    float  x1[NPTS * 64];
    float  x2[NPTS * 64];
    float  x3[NPTS * 64];
    float  x4[NPTS * 64];
    float  t4[NPTS * 128];
    float  t3[NPTS * 128];
    float  t2[NPTS * 64];
    float  t1[NPTS * 64];
    float  M[NGRP * 64];             // group means of x1_final
    float  b10[128];                 // W10[:, :128] @ g
    float  gmax[128];
    double sum[13 * 128];
    double sq[13 * 128];
};
__device__ Scratch g_s;

// ---------------- helpers ----------------
__device__ __forceinline__ float lrelu(float v) { return v >= 0.f ? v : 0.2f * v; }

__device__ __forceinline__ void atomicMaxFloat(float* addr, float val) {
    int* ai = (int*)addr;
    int old = *ai;
    while (__int_as_float(old) < val) {
        int assumed = old;
        old = atomicCAS(ai, assumed, __float_as_int(val));
        if (old == assumed) break;
    }
}

// ---------------- kernel 0: zero stats ----------------
__global__ void zero_kernel(double* sum, double* sq, float* gmax) {
    int t = blockIdx.x * blockDim.x + threadIdx.x;
    if (t < 13 * 128) { sum[t] = 0.0; sq[t] = 0.0; }
    if (t < 128) gmax[t] = -INFINITY;
}

// ---------------- kernel 1: kNN via per-point bitonic sort ----------------
// Block i = point i. Sort the 1024 same-group distances ascending (tie: index).
__global__ void knn_kernel(const float* __restrict__ x, int* __restrict__ idxo) {
    __shared__ float px[GRP], py[GRP], pz[GRP];
    __shared__ float sk[GRP];
    __shared__ int   si[GRP];
    const int i    = blockIdx.x;
    const int base = (i >> 10) << 10;
    const int tid  = threadIdx.x;  // 512

    for (int j = tid; j < GRP; j += 512) {
        px[j] = x[(base + j) * 3 + 0];
        py[j] = x[(base + j) * 3 + 1];
        pz[j] = x[(base + j) * 3 + 2];
    }
    __syncthreads();

    const int li = i - base;
    const float xi = px[li], yi = py[li], zi = pz[li];
    const float sqi = xi * xi + yi * yi + zi * zi;
    for (int j = tid; j < GRP; j += 512) {
        float sqj = px[j] * px[j] + py[j] * py[j] + pz[j] * pz[j];
        float dot = xi * px[j] + yi * py[j] + zi * pz[j];
        float d = sqi + sqj - 2.f * dot;
        sk[j] = (j == li) ? INFINITY : d;
        si[j] = base + j;
    }
    __syncthreads();

    for (int size = 2; size <= GRP; size <<= 1) {
        for (int stride = size >> 1; stride > 0; stride >>= 1) {
            int t = tid;
            int pos = 2 * t - (t & (stride - 1));
            int q = pos + stride;
            bool up = ((pos & size) == 0);
            float k0 = sk[pos], k1 = sk[q];
            int   i0 = si[pos], i1 = si[q];
            bool less01 = (k0 < k1) || (k0 == k1 && i0 < i1);
            if (up != less01) {   // swap when out of desired order
                sk[pos] = k1; sk[q] = k0;
                si[pos] = i1; si[q] = i0;
            }
            __syncthreads();
        }
    }
    for (int k = tid; k < KNN_TOT; k += 512)
        idxo[i * KNN_TOT + k] = si[k];
}

// ---------------- kernel: A/B precompute for an edge block ----------------
__global__ void ab_kernel(const float* __restrict__ X, int Cin,
                          const float* __restrict__ W,
                          float* __restrict__ A, float* __restrict__ B) {
    int t = blockIdx.x * blockDim.x + threadIdx.x;
    if (t >= NPTS * 64) return;
    int n = t >> 6, o = t & 63;
    const float* xr = X + n * Cin;
    const float* wr = W + o * 2 * Cin;
    float a = 0.f, b = 0.f;
    for (int c = 0; c < Cin; c++) {
        float xv = xr[c];
        a = fmaf(wr[c], xv, a);
        b = fmaf(wr[Cin + c], xv, b);
    }
    A[t] = a;
    B[t] = b - a;
}

// ---------------- kernel: y1 statistics (sum, sumsq per channel) ----------------
__global__ void stats1_kernel(const float* __restrict__ A, const float* __restrict__ B,
                              const int* __restrict__ idx, int stride,
                              double* __restrict__ gsum, double* __restrict__ gsq) {
    __shared__ float r1[64], r2[64];
    __shared__ int jj[4][20];
    int tid = threadIdx.x;   // 256
    int nl = tid >> 6, c = tid & 63;
    int n = blockIdx.x * 4 + nl;
    if (tid < 64) { r1[tid] = 0.f; r2[tid] = 0.f; }
    if (tid < 80) {
        int a = tid / 20, k = tid % 20;
        jj[a][k] = idx[(blockIdx.x * 4 + a) * KNN_TOT + k * stride];
    }
    __syncthreads();
    float bv = B[n * 64 + c];
    float s1 = 0.f, s2 = 0.f;
    #pragma unroll
    for (int k = 0; k < 20; k++) {
        float h = A[jj[nl][k] * 64 + c] + bv;
        s1 += h;
        s2 = fmaf(h, h, s2);
    }
    atomicAdd(&r1[c], s1);
    atomicAdd(&r2[c], s2);
    __syncthreads();
    if (tid < 64) {
        atomicAdd(&gsum[tid], (double)r1[tid]);
        atomicAdd(&gsq[tid], (double)r2[tid]);
    }
}

// ---------------- kernel: conv2 + max-over-k + y2 stats ----------------
// One block per point n; 128 threads: o = tid&63, khalf = tid>>6 (10 k's each).
__global__ void conv2max_kernel(const float* __restrict__ A, const float* __restrict__ B,
                                const int* __restrict__ idx, int stride,
                                const double* __restrict__ s1sum, const double* __restrict__ s1sq,
                                const float* __restrict__ Wb,
                                float* __restrict__ z,
                                double* __restrict__ osum, double* __restrict__ osq) {
    __shared__ float h[20][64];
    __shared__ float mean[64], istd[64];
    __shared__ int jj[20];
    __shared__ float red[128];
    const int n = blockIdx.x;
    const int tid = threadIdx.x;

    if (tid < 64) {
        double m = s1sum[tid] / (double)MPAIR;
        double v = s1sq[tid] / (double)MPAIR - m * m;
        mean[tid] = (float)m;
        istd[tid] = (float)(1.0 / sqrt(v + EPSV));
    }
    if (tid >= 64 && tid < 84)
        jj[tid - 64] = idx[n * KNN_TOT + (tid - 64) * stride];
    __syncthreads();

    for (int e = tid; e < 1280; e += 128) {
        int k = e >> 6, c = e & 63;
        float raw = A[jj[k] * 64 + c] + B[n * 64 + c];
        h[k][c] = lrelu((raw - mean[c]) * istd[c]);
    }
    __syncthreads();

    const int o = tid & 63, kh = tid >> 6;
    float y[10];
    #pragma unroll
    for (int q = 0; q < 10; q++) y[q] = 0.f;
    const float4* wrow = (const float4*)(Wb + o * 64);
    #pragma unroll
    for (int cq = 0; cq < 16; cq++) {
        float4 w = wrow[cq];
        #pragma unroll
        for (int q = 0; q < 10; q++) {
            float4 hv = *(const float4*)&h[kh * 10 + q][cq * 4];
            y[q] = fmaf(w.x, hv.x, y[q]);
            y[q] = fmaf(w.y, hv.y, y[q]);
            y[q] = fmaf(w.z, hv.z, y[q]);
            y[q] = fmaf(w.w, hv.w, y[q]);
        }
    }
    float ls = 0.f, lq = 0.f, lm = -INFINITY;
    #pragma unroll
    for (int q = 0; q < 10; q++) {
        ls += y[q];
        lq = fmaf(y[q], y[q], lq);
        lm = fmaxf(lm, y[q]);
    }
    red[tid] = ls; __syncthreads();
    if (tid < 64) atomicAdd(&osum[tid], (double)(red[tid] + red[tid + 64]));
    __syncthreads();
    red[tid] = lq; __syncthreads();
    if (tid < 64) atomicAdd(&osq[tid], (double)(red[tid] + red[tid + 64]));
    __syncthreads();
    red[tid] = lm; __syncthreads();
    if (tid < 64) z[n * 64 + tid] = fmaxf(red[tid], red[tid + 64]);
}

// ---------------- kernel: edge-block finalize (norm + lrelu + residual) ----------------
__global__ void edgefin_kernel(const float* __restrict__ z,
                               const double* __restrict__ s, const double* __restrict__ q,
                               const float* __restrict__ res,
                               float* __restrict__ xo) {
    __shared__ float mean[64], istd[64];
    int tid = threadIdx.x;   // 256
    if (tid < 64) {
        double m = s[tid] / (double)MPAIR;
        double v = q[tid] / (double)MPAIR - m * m;
        mean[tid] = (float)m;
        istd[tid] = (float)(1.0 / sqrt(v + EPSV));
    }
    __syncthreads();
    int t0 = blockIdx.x * 256 + tid;
    int c = t0 & 63;
    float v = lrelu((z[t0] - mean[c]) * istd[c]);
    if (res) v += res[t0];
    xo[t0] = v;
}

// ---------------- kernel: g stats (u = W9 @ concat(x1..x4); sum/sq/max over n) ----------------
__global__ void gstat_kernel(const float* __restrict__ x1, const float* __restrict__ x2,
                             const float* __restrict__ x3, const float* __restrict__ x4,
                             const float* __restrict__ W9,
                             double* __restrict__ gsum, double* __restrict__ gsq,
                             float* __restrict__ gmax) {
    __shared__ float f[256];
    int tid = threadIdx.x;   // 128
    int n0 = blockIdx.x * 32;
    float ls = 0.f, lq = 0.f, lm = -INFINITY;
    for (int nn = 0; nn < 32; nn++) {
        int n = n0 + nn;
        f[tid]       = (tid < 64) ? x1[n * 64 + tid] : x2[n * 64 + tid - 64];
        f[tid + 128] = (tid < 64) ? x3[n * 64 + tid] : x4[n * 64 + tid - 64];
        __syncthreads();
        float acc = 0.f;
        const float4* wr = (const float4*)(W9 + tid * 256);
        #pragma unroll 8
        for (int cq = 0; cq < 64; cq++) {
            float4 w = wr[cq];
            float4 fv = *(const float4*)&f[cq * 4];
            acc = fmaf(w.x, fv.x, acc);
            acc = fmaf(w.y, fv.y, acc);
            acc = fmaf(w.z, fv.z, acc);
            acc = fmaf(w.w, fv.w, acc);
        }
        ls += acc;
        lq = fmaf(acc, acc, lq);
        lm = fmaxf(lm, acc);
        __syncthreads();
    }
    atomicAdd(&gsum[tid], (double)ls);
    atomicAdd(&gsq[tid], (double)lq);
    atomicMaxFloat(&gmax[tid], lm);
}

// ---------------- kernel: g finalize + b10 = W10[:, :128] @ g ----------------
__global__ void gfinal_kernel(const double* __restrict__ gsum, const double* __restrict__ gsq,
                              const float* __restrict__ gmax,
                              const float* __restrict__ W10, float* __restrict__ b10) {
    __shared__ float gg[128];
    int tid = threadIdx.x;   // 128
    double m = gsum[tid] / 8192.0;
    double v = gsq[tid] / 8192.0 - m * m;
    float u = (gmax[tid] - (float)m) * (float)(1.0 / sqrt(v + EPSV));
    gg[tid] = lrelu(u);
    __syncthreads();
    float acc = 0.f;
    #pragma unroll 4
    for (int c = 0; c < 128; c++) acc = fmaf(W10[tid * 192 + c], gg[c], acc);
    b10[tid] = acc;
}

// ---------------- kernel: generic 1d block (GEMM + stats); norm on in1 optional ----------------
__global__ void mm1d_kernel(int rowlen,
                            const float* __restrict__ in1, int C1, int woff1,
                            const double* __restrict__ s1, const double* __restrict__ q1,
                            const float* __restrict__ in2, int C2, int woff2,
                            const float* __restrict__ W, const float* __restrict__ bias,
                            float* __restrict__ out,
                            double* __restrict__ osum, double* __restrict__ osq) {
    __shared__ float mean[128], istd[128];
    __shared__ float f[192];
    const int O = blockDim.x;
    const int tid = threadIdx.x;
    if (s1) {
        for (int c = tid; c < C1; c += O) {
            double m = s1[c] / 8192.0;
            double v = q1[c] / 8192.0 - m * m;
            mean[c] = (float)m;
            istd[c] = (float)(1.0 / sqrt(v + EPSV));
        }
    }
    __syncthreads();
    float ls = 0.f, lq = 0.f;
    for (int nn = 0; nn < 8; nn++) {
        int n = blockIdx.x * 8 + nn;
        for (int c = tid; c < C1; c += O) {
            float v = in1[n * C1 + c];
            if (s1) v = lrelu((v - mean[c]) * istd[c]);
            f[c] = v;
        }
        for (int c = tid; c < C2; c += O) f[C1 + c] = in2[n * C2 + c];
        __syncthreads();
        float acc = bias ? bias[tid] : 0.f;
        const float* wr = W + tid * rowlen;
        for (int c = 0; c < C1; c++) acc = fmaf(wr[woff1 + c], f[c], acc);
        for (int c = 0; c < C2; c++) acc = fmaf(wr[woff2 + c], f[C1 + c], acc);
        out[n * O + tid] = acc;
        ls += acc;
        lq = fmaf(acc, acc, lq);
        __syncthreads();
    }
    atomicAdd(&osum[tid], (double)ls);
    atomicAdd(&osq[tid], (double)lq);
}

// ---------------- kernel: per-group means of normalized t1 ----------------
__global__ void gmean_kernel(const float* __restrict__ t1,
                             const double* __restrict__ s, const double* __restrict__ q,
                             float* __restrict__ Mo) {
    __shared__ float mean[64], istd[64];
    __shared__ float r[256];
    int tid = threadIdx.x;   // 256
    int g = blockIdx.x;
    if (tid < 64) {
        double m = s[tid] / 8192.0;
        double v = q[tid] / 8192.0 - m * m;
        mean[tid] = (float)m;
        istd[tid] = (float)(1.0 / sqrt(v + EPSV));
    }
    __syncthreads();
    int c = tid & 63, a = tid >> 6;
    float acc = 0.f;
    for (int nn = a; nn < 1024; nn += 4) {
        int n = g * 1024 + nn;
        acc += lrelu((t1[n * 64 + c] - mean[c]) * istd[c]);
    }
    r[tid] = acc;
    __syncthreads();
    if (tid < 64)
        Mo[g * 64 + tid] = (r[tid] + r[tid + 64] + r[tid + 128] + r[tid + 192]) * (1.f / 1024.f);
}

// ---------------- kernel: final out = Wr @ M^T ----------------
__global__ void out_kernel(const float* __restrict__ Wr, const float* __restrict__ Mo,
                           float* __restrict__ out) {
    int tid = threadIdx.x;   // 1024
    int t = tid >> 7, cd = tid & 127;
    float acc = 0.f;
    #pragma unroll 4
    for (int c = 0; c < 64; c++) acc = fmaf(Wr[cd * 64 + c], Mo[t * 64 + c], acc);
    out[t * 128 + cd] = acc;
}

// ---------------- host ----------------
extern "C" void kernel_launch(void* const* d_in, const int* in_sizes, int n_in,
                              void* d_out, int out_size) {
    const float* x = (const float*)d_in[0];
    int base = 2;
    if (n_in >= 3 && in_sizes[2] == 1) base = 3;   // skip n_obj scalar if present
    const float* W[14];
    for (int i = 0; i < 14; i++) W[i] = (const float*)d_in[base + i];
    // W[0..7]=W1..W8, W[8]=W9, W[9]=W10, W[10]=W11, W[11]=W12, W[12]=W13, W[13]=Wr

    Scratch* S = nullptr;
    cudaGetSymbolAddress((void**)&S, g_s);
    float* out = (float*)d_out;

    double* SUM = S->sum;
    double* SQ  = S->sq;

    zero_kernel<<<7, 256>>>(SUM, SQ, S->gmax);
    knn_kernel<<<NPTS, 512>>>(x, S->idx);

    const int strides[4] = {1, 2, 6, 18};
    const float* xin[4]  = {x, S->x1, S->x2, S->x3};
    const int    cins[4] = {3, 64, 64, 64};
    float*       xout[4] = {S->x1, S->x2, S->x3, S->x4};
    const float* resi[4] = {nullptr, S->x1, S->x2, S->x3};

    for (int e = 0; e < 4; e++) {
        const float* Wa = W[2 * e];
        const float* Wb = W[2 * e + 1];
        int s0 = 2 * e, s1 = 2 * e + 1;
        ab_kernel<<<NPTS * 64 / 256, 256>>>(xin[e], cins[e], Wa, S->A, S->B);
        stats1_kernel<<<NPTS / 4, 256>>>(S->A, S->B, S->idx, strides[e],
                                         SUM + s0 * 128, SQ + s0 * 128);
        conv2max_kernel<<<NPTS, 128>>>(S->A, S->B, S->idx, strides[e],
                                       SUM + s0 * 128, SQ + s0 * 128, Wb,
                                       S->z, SUM + s1 * 128, SQ + s1 * 128);
        edgefin_kernel<<<NPTS * 64 / 256, 256>>>(S->z, SUM + s1 * 128, SQ + s1 * 128,
                                                 resi[e], xout[e]);
    }

    gstat_kernel<<<NPTS / 32, 128>>>(S->x1, S->x2, S->x3, S->x4, W[8],
                                     SUM + 8 * 128, SQ + 8 * 128, S->gmax);
    gfinal_kernel<<<1, 128>>>(SUM + 8 * 128, SQ + 8 * 128, S->gmax, W[9], S->b10);

    // x4_new = lrelu(norm(W10 @ [g; x4]))  -> t4 raw + slot 9
    mm1d_kernel<<<NPTS / 8, 128>>>(192, S->x4, 64, 128, nullptr, nullptr,
                                   nullptr, 0, 0, W[9], S->b10,
                                   S->t4, SUM + 9 * 128, SQ + 9 * 128);
    // x3_new = W11 @ [norm(t4); x3] -> t3 + slot 10
    mm1d_kernel<<<NPTS / 8, 128>>>(192, S->t4, 128, 0, SUM + 9 * 128, SQ + 9 * 128,
                                   S->x3, 64, 128, W[10], nullptr,
                                   S->t3, SUM + 10 * 128, SQ + 10 * 128);
    // x2_new = W12 @ [norm(t3); x2] -> t2 + slot 11
    mm1d_kernel<<<NPTS / 8, 64>>>(192, S->t3, 128, 0, SUM + 10 * 128, SQ + 10 * 128,
                                  S->x2, 64, 128, W[11], nullptr,
                                  S->t2, SUM + 11 * 128, SQ + 11 * 128);
    // x1_new = W13 @ [norm(t2); x1] -> t1 + slot 12
    mm1d_kernel<<<NPTS / 8, 64>>>(128, S->t2, 64, 0, SUM + 11 * 128, SQ + 11 * 128,
                                  S->x1, 64, 64, W[12], nullptr,
                                  S->t1, SUM + 12 * 128, SQ + 12 * 128);

    gmean_kernel<<<NGRP, 256>>>(S->t1, SUM + 12 * 128, SQ + 12 * 128, S->M);
    out_kernel<<<1, 1024>>>(W[13], S->M, out);
}

// round 2
// speedup vs baseline: 3.3002x; 3.3002x over previous
#include <cuda_runtime.h>
#include <math.h>

#define NPTS 8192
#define GRP  1024
#define NGRP 8
#define KNN_TOT 360
#define MPAIR (NPTS * 20)
#define EPSV 1e-5

typedef unsigned long long u64;

// ---------------- scratch (static device memory; no allocation) ----------------
struct Scratch {
    int    idx[NPTS * KNN_TOT];
    float  A[NPTS * 64];
    float  B[NPTS * 64];
    float  z[NPTS * 64];
    float  x1[NPTS * 64];
    float  x2[NPTS * 64];
    float  x3[NPTS * 64];
    float  x4[NPTS * 64];
    float  t4[NPTS * 128];
    float  t3[NPTS * 128];
    float  t2[NPTS * 64];
    float  t1[NPTS * 64];
    float  M[NGRP * 64];
    float  b10[128];
    float  gmax[128];
    double sum[13 * 128];
    double sq[13 * 128];
};
__device__ Scratch g_s;

// ---------------- helpers ----------------
__device__ __forceinline__ float lrelu(float v) { return v >= 0.f ? v : 0.2f * v; }

__device__ __forceinline__ void ffma2(u64 &d, u64 a, u64 b) {
    asm("fma.rn.f32x2 %0, %1, %2, %0;" : "+l"(d) : "l"(a), "l"(b));
}
__device__ __forceinline__ u64 pk2(float x, float y) {
    return (u64)__float_as_uint(x) | ((u64)__float_as_uint(y) << 32);
}
__device__ __forceinline__ float f2lo(u64 v) { return __uint_as_float((unsigned)v); }
__device__ __forceinline__ float f2hi(u64 v) { return __uint_as_float((unsigned)(v >> 32)); }

__device__ __forceinline__ void atomicMaxFloat(float* addr, float val) {
    int* ai = (int*)addr;
    int old = *ai;
    while (__int_as_float(old) < val) {
        int assumed = old;
        old = atomicCAS(ai, assumed, __float_as_int(val));
        if (old == assumed) break;
    }
}

// ---------------- zero stats ----------------
__global__ void zero_kernel(double* sum, double* sq, float* gmax) {
    int t = blockIdx.x * blockDim.x + threadIdx.x;
    if (t < 13 * 128) { sum[t] = 0.0; sq[t] = 0.0; }
    if (t < 128) gmax[t] = -INFINITY;
}

// ---------------- kNN: per-point bitonic sort on packed u64 keys ----------------
__global__ void __launch_bounds__(512) knn_kernel(const float* __restrict__ x,
                                                  int* __restrict__ idxo) {
    __shared__ float px[GRP], py[GRP], pz[GRP];
    __shared__ u64 sk[GRP];
    const int i    = blockIdx.x;
    const int base = i & ~(GRP - 1);
    const int tid  = threadIdx.x;  // 512

    for (int j = tid; j < GRP; j += 512) {
        px[j] = x[(base + j) * 3 + 0];
        py[j] = x[(base + j) * 3 + 1];
        pz[j] = x[(base + j) * 3 + 2];
    }
    __syncthreads();

    const int li = i - base;
    const float xi = px[li], yi = py[li], zi = pz[li];
    const float sqi = xi * xi + yi * yi + zi * zi;
    for (int j = tid; j < GRP; j += 512) {
        float sqj = px[j] * px[j] + py[j] * py[j] + pz[j] * pz[j];
        float dot = xi * px[j] + yi * py[j] + zi * pz[j];
        float d = sqi + sqj - 2.f * dot;
        if (j == li) d = INFINITY;
        unsigned b = __float_as_uint(d);
        b ^= (b & 0x80000000u) ? 0xFFFFFFFFu : 0x80000000u;  // order-preserving
        sk[j] = ((u64)b << 32) | (unsigned)j;
    }
    __syncthreads();

    for (int size = 2; size <= GRP; size <<= 1) {
        for (int stride = size >> 1; stride > 0; stride >>= 1) {
            if (stride >= 32) __syncthreads(); else __syncwarp();
            int pos = 2 * tid - (tid & (stride - 1));
            bool up = ((pos & size) == 0);
            u64 a = sk[pos], b = sk[pos + stride];
            if ((a < b) != up) { sk[pos] = b; sk[pos + stride] = a; }
        }
    }
    __syncthreads();
    for (int k = tid; k < KNN_TOT; k += 512)
        idxo[i * KNN_TOT + k] = base + (int)(sk[k] & 0xFFFFFFFFu);
}

// ---------------- A/B precompute (W in smem, 16 points/block) ----------------
__global__ void __launch_bounds__(256) ab_kernel(const float* __restrict__ X, int Cin,
                                                 const float* __restrict__ W,
                                                 float* __restrict__ A, float* __restrict__ B) {
    __shared__ float a_s[64 * 64];
    __shared__ float d_s[64 * 64];
    __shared__ float xs[16 * 64];
    const int tid = threadIdx.x;
    const int n0 = blockIdx.x * 16;

    for (int e = tid; e < Cin * 64; e += 256) {
        int c = e >> 6, o = e & 63;
        float wn = W[o * 2 * Cin + c];
        float wc = W[o * 2 * Cin + Cin + c];
        a_s[c * 64 + o] = wn;
        d_s[c * 64 + o] = wc - wn;
    }
    for (int e = tid; e < 16 * Cin; e += 256) {
        int p = e / Cin, c = e - p * Cin;
        xs[p * 64 + c] = X[(n0 + p) * Cin + c];
    }
    __syncthreads();

    const int o = tid & 63, pg = tid >> 6;
    float aa[4] = {0.f, 0.f, 0.f, 0.f}, bb[4] = {0.f, 0.f, 0.f, 0.f};
    for (int c = 0; c < Cin; c++) {
        float wn = a_s[c * 64 + o], wd = d_s[c * 64 + o];
        #pragma unroll
        for (int q = 0; q < 4; q++) {
            float xv = xs[(pg * 4 + q) * 64 + c];
            aa[q] = fmaf(wn, xv, aa[q]);
            bb[q] = fmaf(wd, xv, bb[q]);
        }
    }
    #pragma unroll
    for (int q = 0; q < 4; q++) {
        int n = n0 + pg * 4 + q;
        A[n * 64 + o] = aa[q];
        B[n * 64 + o] = bb[q];
    }
}

// ---------------- y1 statistics (float4, 16 points/block) ----------------
__global__ void __launch_bounds__(256) stats1_kernel(const float4* __restrict__ A4,
                                                     const float4* __restrict__ B4,
                                                     const int* __restrict__ idx, int stride,
                                                     double* __restrict__ gsum,
                                                     double* __restrict__ gsq) {
    __shared__ int jj[16][20];
    __shared__ float r1[64], r2[64];
    const int tid = threadIdx.x;   // 256
    const int n0 = blockIdx.x * 16;
    if (tid < 64) { r1[tid] = 0.f; r2[tid] = 0.f; }
    for (int e = tid; e < 320; e += 256) {
        int p = e / 20, k = e - p * 20;
        jj[p][k] = idx[(n0 + p) * KNN_TOT + k * stride];
    }
    __syncthreads();
    const int p = tid >> 4, c4 = tid & 15;
    float4 bv = B4[(n0 + p) * 16 + c4];
    float4 s1 = {0.f, 0.f, 0.f, 0.f}, s2 = {0.f, 0.f, 0.f, 0.f};
    #pragma unroll
    for (int k = 0; k < 20; k++) {
        float4 a = A4[jj[p][k] * 16 + c4];
        float hx = a.x + bv.x, hy = a.y + bv.y, hz = a.z + bv.z, hw = a.w + bv.w;
        s1.x += hx; s1.y += hy; s1.z += hz; s1.w += hw;
        s2.x = fmaf(hx, hx, s2.x); s2.y = fmaf(hy, hy, s2.y);
        s2.z = fmaf(hz, hz, s2.z); s2.w = fmaf(hw, hw, s2.w);
    }
    atomicAdd(&r1[c4 * 4 + 0], s1.x); atomicAdd(&r1[c4 * 4 + 1], s1.y);
    atomicAdd(&r1[c4 * 4 + 2], s1.z); atomicAdd(&r1[c4 * 4 + 3], s1.w);
    atomicAdd(&r2[c4 * 4 + 0], s2.x); atomicAdd(&r2[c4 * 4 + 1], s2.y);
    atomicAdd(&r2[c4 * 4 + 2], s2.z); atomicAdd(&r2[c4 * 4 + 3], s2.w);
    __syncthreads();
    if (tid < 64) {
        atomicAdd(&gsum[tid], (double)r1[tid]);
        atomicAdd(&gsq[tid], (double)r2[tid]);
    }
}

// ---------------- conv2 + max-over-k + y2 stats (16 pts/block, f32x2) ----------------
__global__ void __launch_bounds__(256) conv2max_kernel(
    const float4* __restrict__ A4, const float4* __restrict__ B4,
    const int* __restrict__ idx, int stride,
    const double* __restrict__ s1sum, const double* __restrict__ s1sq,
    const float4* __restrict__ Wb4,
    float* __restrict__ z,
    double* __restrict__ osum, double* __restrict__ osq) {
    __shared__ __align__(16) float h[20][64];
    __shared__ float mean[64], istd[64];
    __shared__ int jj[16][20];
    __shared__ float red[256];
    const int tid = threadIdx.x;     // 256
    const int n0 = blockIdx.x * 16;
    const int o = tid & 63, kh = tid >> 6;

    u64 w2[32];
    #pragma unroll
    for (int cq = 0; cq < 16; cq++) {
        float4 w = Wb4[o * 16 + cq];
        w2[cq * 2]     = pk2(w.x, w.y);
        w2[cq * 2 + 1] = pk2(w.z, w.w);
    }
    if (tid < 64) {
        double m = s1sum[tid] / (double)MPAIR;
        double v = s1sq[tid] / (double)MPAIR - m * m;
        mean[tid] = (float)m;
        istd[tid] = (float)(1.0 / sqrt(v + EPSV));
    }
    for (int e = tid; e < 320; e += 256) {
        int p = e / 20, k = e - p * 20;
        jj[p][k] = idx[(n0 + p) * KNN_TOT + k * stride];
    }
    __syncthreads();

    float sA = 0.f, sQ = 0.f;
    for (int p = 0; p < 16; p++) {
        int n = n0 + p;
        for (int e = tid; e < 320; e += 256) {
            int k = e >> 4, cq = e & 15;
            float4 a = A4[jj[p][k] * 16 + cq];
            float4 b = B4[n * 16 + cq];
            int c0 = cq * 4;
            float4 r;
            r.x = lrelu((a.x + b.x - mean[c0 + 0]) * istd[c0 + 0]);
            r.y = lrelu((a.y + b.y - mean[c0 + 1]) * istd[c0 + 1]);
            r.z = lrelu((a.z + b.z - mean[c0 + 2]) * istd[c0 + 2]);
            r.w = lrelu((a.w + b.w - mean[c0 + 3]) * istd[c0 + 3]);
            *(float4*)&h[k][c0] = r;
        }
        __syncthreads();

        u64 acc[10];
        #pragma unroll
        for (int q = 0; q < 10; q++) acc[q] = 0ull;
        #pragma unroll
        for (int cq = 0; cq < 16; cq++) {
            #pragma unroll
            for (int q = 0; q < 5; q++) {
                const u64* hv = (const u64*)&h[kh * 5 + q][cq * 4];
                ffma2(acc[q * 2],     w2[cq * 2],     hv[0]);
                ffma2(acc[q * 2 + 1], w2[cq * 2 + 1], hv[1]);
            }
        }
        float ymax = -INFINITY;
        #pragma unroll
        for (int q = 0; q < 5; q++) {
            float y = (f2lo(acc[q * 2]) + f2hi(acc[q * 2])) +
                      (f2lo(acc[q * 2 + 1]) + f2hi(acc[q * 2 + 1]));
            sA += y;
            sQ = fmaf(y, y, sQ);
            ymax = fmaxf(ymax, y);
        }
        red[tid] = ymax;
        __syncthreads();
        if (tid < 64)
            z[n * 64 + tid] = fmaxf(fmaxf(red[tid], red[tid + 64]),
                                    fmaxf(red[tid + 128], red[tid + 192]));
        __syncthreads();
    }
    red[tid] = sA;
    __syncthreads();
    if (tid < 64)
        atomicAdd(&osum[tid], (double)(red[tid] + red[tid + 64] + red[tid + 128] + red[tid + 192]));
    __syncthreads();
    red[tid] = sQ;
    __syncthreads();
    if (tid < 64)
        atomicAdd(&osq[tid], (double)(red[tid] + red[tid + 64] + red[tid + 128] + red[tid + 192]));
}

// ---------------- edge-block finalize ----------------
__global__ void edgefin_kernel(const float* __restrict__ z,
                               const double* __restrict__ s, const double* __restrict__ q,
                               const float* __restrict__ res,
                               float* __restrict__ xo) {
    __shared__ float mean[64], istd[64];
    int tid = threadIdx.x;   // 256
    if (tid < 64) {
        double m = s[tid] / (double)MPAIR;
        double v = q[tid] / (double)MPAIR - m * m;
        mean[tid] = (float)m;
        istd[tid] = (float)(1.0 / sqrt(v + EPSV));
    }
    __syncthreads();
    int t0 = blockIdx.x * 256 + tid;
    int c = t0 & 63;
    float v = lrelu((z[t0] - mean[c]) * istd[c]);
    if (res) v += res[t0];
    xo[t0] = v;
}

// ---------------- g stats: W9 in smem, 4-pt ILP, f32x2 ----------------
__global__ void __launch_bounds__(128) gstat_kernel(
    const float* __restrict__ x1, const float* __restrict__ x2,
    const float* __restrict__ x3, const float* __restrict__ x4,
    const float* __restrict__ W9,
    double* __restrict__ gsum, double* __restrict__ gsq, float* __restrict__ gmax) {
    extern __shared__ float ws[];               // 128 * 258
    __shared__ __align__(16) float f[4 * 256];
    const int tid = threadIdx.x;  // 128
    for (int e = tid; e < 128 * 256; e += 128) {
        int o = e >> 8, c = e & 255;
        ws[o * 258 + c] = W9[e];
    }
    __syncthreads();
    float ls = 0.f, lq = 0.f, lm = -INFINITY;
    const int n0 = blockIdx.x * 64;
    const u64* wrow = (const u64*)(ws + tid * 258);
    for (int it = 0; it < 16; it++) {
        int nb = n0 + it * 4;
        for (int e = tid; e < 1024; e += 128) {
            int p = e >> 8, c = e & 255;
            const float* src = (c < 64) ? x1 : (c < 128) ? x2 : (c < 192) ? x3 : x4;
            f[e] = src[(nb + p) * 64 + (c & 63)];
        }
        __syncthreads();
        u64 acc[4] = {0ull, 0ull, 0ull, 0ull};
        const u64* f2 = (const u64*)f;
        #pragma unroll 8
        for (int c2 = 0; c2 < 128; c2++) {
            u64 w = wrow[c2];
            #pragma unroll
            for (int q = 0; q < 4; q++) ffma2(acc[q], w, f2[q * 128 + c2]);
        }
        #pragma unroll
        for (int q = 0; q < 4; q++) {
            float y = f2lo(acc[q]) + f2hi(acc[q]);
            ls += y;
            lq = fmaf(y, y, lq);
            lm = fmaxf(lm, y);
        }
        __syncthreads();
    }
    atomicAdd(&gsum[tid], (double)ls);
    atomicAdd(&gsq[tid], (double)lq);
    atomicMaxFloat(&gmax[tid], lm);
}

// ---------------- g finalize + b10 ----------------
__global__ void gfinal_kernel(const double* __restrict__ gsum, const double* __restrict__ gsq,
                              const float* __restrict__ gmax,
                              const float* __restrict__ W10, float* __restrict__ b10) {
    __shared__ float gg[128];
    int tid = threadIdx.x;   // 128
    double m = gsum[tid] / 8192.0;
    double v = gsq[tid] / 8192.0 - m * m;
    float u = (gmax[tid] - (float)m) * (float)(1.0 / sqrt(v + EPSV));
    gg[tid] = lrelu(u);
    __syncthreads();
    float acc = 0.f;
    #pragma unroll 4
    for (int c = 0; c < 128; c++) acc = fmaf(W10[tid * 192 + c], gg[c], acc);
    b10[tid] = acc;
}

// ---------------- generic 1d block: W in smem, 4-pt ILP ----------------
__global__ void __launch_bounds__(128) mm1d_kernel(
    int C1, int woff1, const double* __restrict__ s1, const double* __restrict__ q1,
    const float* __restrict__ in1,
    int C2, int woff2, const float* __restrict__ in2,
    int O, int rowlen, const float* __restrict__ W, const float* __restrict__ bias,
    float* __restrict__ out,
    double* __restrict__ osum, double* __restrict__ osq) {
    extern __shared__ float ws[];       // O * (CT+1)
    __shared__ float f[8 * 192];
    __shared__ float mean[128], istd[128];
    const int tid = threadIdx.x;   // 128
    const int CT = C1 + C2, CP = CT + 1;

    for (int e = tid; e < O * CT; e += 128) {
        int oo = e / CT, cc = e - oo * CT;
        int col = (cc < C1) ? (woff1 + cc) : (woff2 + cc - C1);
        ws[oo * CP + cc] = W[oo * rowlen + col];
    }
    if (s1 && tid < C1) {
        double m = s1[tid] / 8192.0;
        double v = q1[tid] / 8192.0 - m * m;
        mean[tid] = (float)m;
        istd[tid] = (float)(1.0 / sqrt(v + EPSV));
    }
    __syncthreads();

    const int reps = 128 / O;
    const int o = tid & (O - 1);
    const int rep = tid / O;
    const int PG = 4 * reps;
    const int n0 = blockIdx.x * 64;
    float ls = 0.f, lq = 0.f;

    for (int it = 0; it < 64 / PG; it++) {
        int nb = n0 + it * PG;
        for (int e = tid; e < PG * CT; e += 128) {
            int p = e / CT, c = e - p * CT;
            float v;
            if (c < C1) {
                v = in1[(nb + p) * C1 + c];
                if (s1) v = lrelu((v - mean[c]) * istd[c]);
            } else {
                v = in2[(nb + p) * C2 + (c - C1)];
            }
            f[e] = v;
        }
        __syncthreads();
        float acc[4];
        float binit = bias ? bias[o] : 0.f;
        #pragma unroll
        for (int q = 0; q < 4; q++) acc[q] = binit;
        const int pb = rep * 4;
        const float* wr = ws + o * CP;
        for (int c = 0; c < CT; c++) {
            float w = wr[c];
            #pragma unroll
            for (int q = 0; q < 4; q++)
                acc[q] = fmaf(w, f[(pb + q) * CT + c], acc[q]);
        }
        #pragma unroll
        for (int q = 0; q < 4; q++) {
            int n = nb + pb + q;
            out[n * O + o] = acc[q];
            ls += acc[q];
            lq = fmaf(acc[q], acc[q], lq);
        }
        __syncthreads();
    }
    atomicAdd(&osum[o], (double)ls);
    atomicAdd(&osq[o], (double)lq);
}

// ---------------- per-group means of normalized t1 ----------------
__global__ void gmean_kernel(const float* __restrict__ t1,
                             const double* __restrict__ s, const double* __restrict__ q,
                             float* __restrict__ Mo) {
    __shared__ float mean[64], istd[64];
    __shared__ float r[256];
    int tid = threadIdx.x;   // 256
    int g = blockIdx.x;
    if (tid < 64) {
        double m = s[tid] / 8192.0;
        double v = q[tid] / 8192.0 - m * m;
        mean[tid] = (float)m;
        istd[tid] = (float)(1.0 / sqrt(v + EPSV));
    }
    __syncthreads();
    int c = tid & 63, a = tid >> 6;
    float acc = 0.f;
    for (int nn = a; nn < 1024; nn += 4) {
        int n = g * 1024 + nn;
        acc += lrelu((t1[n * 64 + c] - mean[c]) * istd[c]);
    }
    r[tid] = acc;
    __syncthreads();
    if (tid < 64)
        Mo[g * 64 + tid] = (r[tid] + r[tid + 64] + r[tid + 128] + r[tid + 192]) * (1.f / 1024.f);
}

// ---------------- final out = Wr @ M^T ----------------
__global__ void out_kernel(const float* __restrict__ Wr, const float* __restrict__ Mo,
                           float* __restrict__ out) {
    int tid = threadIdx.x;   // 1024
    int t = tid >> 7, cd = tid & 127;
    float acc = 0.f;
    #pragma unroll 4
    for (int c = 0; c < 64; c++) acc = fmaf(Wr[cd * 64 + c], Mo[t * 64 + c], acc);
    out[t * 128 + cd] = acc;
}

// ---------------- host ----------------
extern "C" void kernel_launch(void* const* d_in, const int* in_sizes, int n_in,
                              void* d_out, int out_size) {
    const float* x = (const float*)d_in[0];
    int base = 2;
    if (n_in >= 3 && in_sizes[2] == 1) base = 3;
    const float* W[14];
    for (int i = 0; i < 14; i++) W[i] = (const float*)d_in[base + i];

    Scratch* S = nullptr;
    cudaGetSymbolAddress((void**)&S, g_s);
    float* out = (float*)d_out;

    double* SUM = S->sum;
    double* SQ  = S->sq;

    cudaFuncSetAttribute(gstat_kernel, cudaFuncAttributeMaxDynamicSharedMemorySize, 128 * 258 * 4);
    cudaFuncSetAttribute(mm1d_kernel,  cudaFuncAttributeMaxDynamicSharedMemorySize, 128 * 193 * 4);

    zero_kernel<<<7, 256>>>(SUM, SQ, S->gmax);
    knn_kernel<<<NPTS, 512>>>(x, S->idx);

    const int strides[4] = {1, 2, 6, 18};
    const float* xin[4]  = {x, S->x1, S->x2, S->x3};
    const int    cins[4] = {3, 64, 64, 64};
    float*       xout[4] = {S->x1, S->x2, S->x3, S->x4};
    const float* resi[4] = {nullptr, S->x1, S->x2, S->x3};

    for (int e = 0; e < 4; e++) {
        const float* Wa = W[2 * e];
        const float* Wb = W[2 * e + 1];
        int s0 = 2 * e, s1 = 2 * e + 1;
        ab_kernel<<<NPTS / 16, 256>>>(xin[e], cins[e], Wa, S->A, S->B);
        stats1_kernel<<<NPTS / 16, 256>>>((const float4*)S->A, (const float4*)S->B,
                                          S->idx, strides[e],
                                          SUM + s0 * 128, SQ + s0 * 128);
        conv2max_kernel<<<NPTS / 16, 256>>>((const float4*)S->A, (const float4*)S->B,
                                            S->idx, strides[e],
                                            SUM + s0 * 128, SQ + s0 * 128,
                                            (const float4*)Wb,
                                            S->z, SUM + s1 * 128, SQ + s1 * 128);
        edgefin_kernel<<<NPTS * 64 / 256, 256>>>(S->z, SUM + s1 * 128, SQ + s1 * 128,
                                                 resi[e], xout[e]);
    }

    gstat_kernel<<<128, 128, 128 * 258 * 4>>>(S->x1, S->x2, S->x3, S->x4, W[8],
                                              SUM + 8 * 128, SQ + 8 * 128, S->gmax);
    gfinal_kernel<<<1, 128>>>(SUM + 8 * 128, SQ + 8 * 128, S->gmax, W[9], S->b10);

    // stage 1: t4 = W10 @ [g; x4] (g folded into bias), stats slot 9
    mm1d_kernel<<<128, 128, 128 * 193 * 4>>>(
        64, 128, nullptr, nullptr, S->x4,
        0, 0, nullptr,
        128, 192, W[9], S->b10,
        S->t4, SUM + 9 * 128, SQ + 9 * 128);
    // stage 2: t3 = W11 @ [norm(t4); x3], stats slot 10
    mm1d_kernel<<<128, 128, 128 * 193 * 4>>>(
        128, 0, SUM + 9 * 128, SQ + 9 * 128, S->t4,
        64, 128, S->x3,
        128, 192, W[10], nullptr,
        S->t3, SUM + 10 * 128, SQ + 10 * 128);
    // stage 3: t2 = W12 @ [norm(t3); x2], stats slot 11
    mm1d_kernel<<<128, 128, 64 * 193 * 4>>>(
        128, 0, SUM + 10 * 128, SQ + 10 * 128, S->t3,
        64, 128, S->x2,
        64, 192, W[11], nullptr,
        S->t2, SUM + 11 * 128, SQ + 11 * 128);
    // stage 4: t1 = W13 @ [norm(t2); x1], stats slot 12
    mm1d_kernel<<<128, 128, 64 * 129 * 4>>>(
        64, 0, SUM + 11 * 128, SQ + 11 * 128, S->t2,
        64, 64, S->x1,
        64, 128, W[12], nullptr,
        S->t1, SUM + 12 * 128, SQ + 12 * 128);

    gmean_kernel<<<NGRP, 256>>>(S->t1, SUM + 12 * 128, SQ + 12 * 128, S->M);
    out_kernel<<<1, 1024>>>(W[13], S->M, out);
}

// round 3
// speedup vs baseline: 3.9212x; 1.1882x over previous
#include <cuda_runtime.h>
#include <math.h>

#define NPTS 8192
#define GRP  1024
#define NGRP 8
#define KNN_TOT 360
#define MPAIR (NPTS * 20)
#define EPSV 1e-5

typedef unsigned long long u64;

// ---------------- scratch (static device memory; no allocation) ----------------
struct Scratch {
    int    idx[NPTS * KNN_TOT];
    float  A[NPTS * 64];
    float  B[NPTS * 64];
    float  z[NPTS * 64];
    float  x1[NPTS * 64];
    float  x2[NPTS * 64];
    float  x3[NPTS * 64];
    float  x4[NPTS * 64];
    float  t4[NPTS * 128];
    float  t3[NPTS * 128];
    float  t2[NPTS * 64];
    float  t1[NPTS * 64];
    float  M[NGRP * 64];
    float  b10[128];
    float  gmax[128];
    double sum[13 * 128];
    double sq[13 * 128];
};
__device__ Scratch g_s;

// ---------------- helpers ----------------
__device__ __forceinline__ float lrelu(float v) { return v >= 0.f ? v : 0.2f * v; }

__device__ __forceinline__ void ffma2(u64 &d, u64 a, u64 b) {
    asm("fma.rn.f32x2 %0, %1, %2, %0;" : "+l"(d) : "l"(a), "l"(b));
}
__device__ __forceinline__ u64 pk2(float x, float y) {
    return (u64)__float_as_uint(x) | ((u64)__float_as_uint(y) << 32);
}
__device__ __forceinline__ float f2lo(u64 v) { return __uint_as_float((unsigned)v); }
__device__ __forceinline__ float f2hi(u64 v) { return __uint_as_float((unsigned)(v >> 32)); }

__device__ __forceinline__ u64 umin64(u64 a, u64 b) { return a < b ? a : b; }
__device__ __forceinline__ u64 umax64(u64 a, u64 b) { return a > b ? a : b; }

__device__ __forceinline__ void atomicMaxFloat(float* addr, float val) {
    int* ai = (int*)addr;
    int old = *ai;
    while (__int_as_float(old) < val) {
        int assumed = old;
        old = atomicCAS(ai, assumed, __float_as_int(val));
        if (old == assumed) break;
    }
}

// ---------------- zero stats ----------------
__global__ void zero_kernel(double* sum, double* sq, float* gmax) {
    int t = blockIdx.x * blockDim.x + threadIdx.x;
    if (t < 13 * 128) { sum[t] = 0.0; sq[t] = 0.0; }
    if (t < 128) gmax[t] = -INFINITY;
}

// ---------------- kNN: register/shuffle bitonic sort, 2 elems/thread ----------------
// Block i = point i. XOR-partner bitonic over 1024 packed u64 keys.
// Strides 2..32 via __shfl_xor; only strides 64..512 via smem (10 of 55 passes).
__global__ void __launch_bounds__(512) knn_kernel(const float* __restrict__ x,
                                                  int* __restrict__ idxo) {
    __shared__ __align__(16) ulonglong2 sk[512];
    const int i    = blockIdx.x;
    const int base = i & ~(GRP - 1);
    const int tid  = threadIdx.x;  // 512
    const int li   = i - base;

    const float qx = x[i * 3 + 0], qy = x[i * 3 + 1], qz = x[i * 3 + 2];
    const float sqi = qx * qx + qy * qy + qz * qz;

    u64 k0, k1;
    {
        int j0 = 2 * tid, j1 = 2 * tid + 1;
        float ax = x[(base + j0) * 3 + 0], ay = x[(base + j0) * 3 + 1], az = x[(base + j0) * 3 + 2];
        float bx = x[(base + j1) * 3 + 0], by = x[(base + j1) * 3 + 1], bz = x[(base + j1) * 3 + 2];
        float d0 = sqi + (ax * ax + ay * ay + az * az) - 2.f * (qx * ax + qy * ay + qz * az);
        float d1 = sqi + (bx * bx + by * by + bz * bz) - 2.f * (qx * bx + qy * by + qz * bz);
        if (j0 == li) d0 = INFINITY;
        if (j1 == li) d1 = INFINITY;
        unsigned u0 = __float_as_uint(d0);
        unsigned u1 = __float_as_uint(d1);
        u0 ^= (u0 & 0x80000000u) ? 0xFFFFFFFFu : 0x80000000u;
        u1 ^= (u1 & 0x80000000u) ? 0xFFFFFFFFu : 0x80000000u;
        k0 = ((u64)u0 << 32) | (unsigned)j0;
        k1 = ((u64)u1 << 32) | (unsigned)j1;
    }

    #pragma unroll
    for (int size = 2; size <= GRP; size <<= 1) {
        #pragma unroll
        for (int stride = size >> 1; stride > 0; stride >>= 1) {
            const bool dir = (((2 * tid) & size) != 0);   // descending region
            if (stride == 1) {
                u64 lo = umin64(k0, k1), hi = umax64(k0, k1);
                k0 = dir ? hi : lo;
                k1 = dir ? lo : hi;
            } else if (stride <= 32) {
                const int m = stride >> 1;
                u64 o0 = __shfl_xor_sync(0xFFFFFFFFu, k0, m);
                u64 o1 = __shfl_xor_sync(0xFFFFFFFFu, k1, m);
                const bool keepMin = ((tid & m) == 0) != dir;
                k0 = keepMin ? umin64(k0, o0) : umax64(k0, o0);
                k1 = keepMin ? umin64(k1, o1) : umax64(k1, o1);
            } else {
                const int m = stride >> 1;
                __syncthreads();
                sk[tid] = make_ulonglong2(k0, k1);
                __syncthreads();
                ulonglong2 o = sk[tid ^ m];
                const bool keepMin = ((tid & m) == 0) != dir;
                k0 = keepMin ? umin64(k0, o.x) : umax64(k0, o.x);
                k1 = keepMin ? umin64(k1, o.y) : umax64(k1, o.y);
            }
        }
    }

    if (tid < KNN_TOT / 2) {
        idxo[i * KNN_TOT + 2 * tid]     = base + (int)(k0 & 0xFFFFFFFFu);
        idxo[i * KNN_TOT + 2 * tid + 1] = base + (int)(k1 & 0xFFFFFFFFu);
    }
}

// ---------------- A/B precompute (W in smem, 16 points/block) ----------------
__global__ void __launch_bounds__(256) ab_kernel(const float* __restrict__ X, int Cin,
                                                 const float* __restrict__ W,
                                                 float* __restrict__ A, float* __restrict__ B) {
    __shared__ float a_s[64 * 64];
    __shared__ float d_s[64 * 64];
    __shared__ float xs[16 * 64];
    const int tid = threadIdx.x;
    const int n0 = blockIdx.x * 16;

    for (int e = tid; e < Cin * 64; e += 256) {
        int c = e >> 6, o = e & 63;
        float wn = W[o * 2 * Cin + c];
        float wc = W[o * 2 * Cin + Cin + c];
        a_s[c * 64 + o] = wn;
        d_s[c * 64 + o] = wc - wn;
    }
    for (int e = tid; e < 16 * Cin; e += 256) {
        int p = e / Cin, c = e - p * Cin;
        xs[p * 64 + c] = X[(n0 + p) * Cin + c];
    }
    __syncthreads();

    const int o = tid & 63, pg = tid >> 6;
    float aa[4] = {0.f, 0.f, 0.f, 0.f}, bb[4] = {0.f, 0.f, 0.f, 0.f};
    for (int c = 0; c < Cin; c++) {
        float wn = a_s[c * 64 + o], wd = d_s[c * 64 + o];
        #pragma unroll
        for (int q = 0; q < 4; q++) {
            float xv = xs[(pg * 4 + q) * 64 + c];
            aa[q] = fmaf(wn, xv, aa[q]);
            bb[q] = fmaf(wd, xv, bb[q]);
        }
    }
    #pragma unroll
    for (int q = 0; q < 4; q++) {
        int n = n0 + pg * 4 + q;
        A[n * 64 + o] = aa[q];
        B[n * 64 + o] = bb[q];
    }
}

// ---------------- y1 statistics (float4, 16 points/block) ----------------
__global__ void __launch_bounds__(256) stats1_kernel(const float4* __restrict__ A4,
                                                     const float4* __restrict__ B4,
                                                     const int* __restrict__ idx, int stride,
                                                     double* __restrict__ gsum,
                                                     double* __restrict__ gsq) {
    __shared__ int jj[16][20];
    __shared__ float r1[64], r2[64];
    const int tid = threadIdx.x;   // 256
    const int n0 = blockIdx.x * 16;
    if (tid < 64) { r1[tid] = 0.f; r2[tid] = 0.f; }
    for (int e = tid; e < 320; e += 256) {
        int p = e / 20, k = e - p * 20;
        jj[p][k] = idx[(n0 + p) * KNN_TOT + k * stride];
    }
    __syncthreads();
    const int p = tid >> 4, c4 = tid & 15;
    float4 bv = B4[(n0 + p) * 16 + c4];
    float4 s1 = {0.f, 0.f, 0.f, 0.f}, s2 = {0.f, 0.f, 0.f, 0.f};
    #pragma unroll
    for (int k = 0; k < 20; k++) {
        float4 a = A4[jj[p][k] * 16 + c4];
        float hx = a.x + bv.x, hy = a.y + bv.y, hz = a.z + bv.z, hw = a.w + bv.w;
        s1.x += hx; s1.y += hy; s1.z += hz; s1.w += hw;
        s2.x = fmaf(hx, hx, s2.x); s2.y = fmaf(hy, hy, s2.y);
        s2.z = fmaf(hz, hz, s2.z); s2.w = fmaf(hw, hw, s2.w);
    }
    atomicAdd(&r1[c4 * 4 + 0], s1.x); atomicAdd(&r1[c4 * 4 + 1], s1.y);
    atomicAdd(&r1[c4 * 4 + 2], s1.z); atomicAdd(&r1[c4 * 4 + 3], s1.w);
    atomicAdd(&r2[c4 * 4 + 0], s2.x); atomicAdd(&r2[c4 * 4 + 1], s2.y);
    atomicAdd(&r2[c4 * 4 + 2], s2.z); atomicAdd(&r2[c4 * 4 + 3], s2.w);
    __syncthreads();
    if (tid < 64) {
        atomicAdd(&gsum[tid], (double)r1[tid]);
        atomicAdd(&gsq[tid], (double)r2[tid]);
    }
}

// ---------------- conv2 + max-over-k + y2 stats (16 pts/block, f32x2) ----------------
__global__ void __launch_bounds__(256) conv2max_kernel(
    const float4* __restrict__ A4, const float4* __restrict__ B4,
    const int* __restrict__ idx, int stride,
    const double* __restrict__ s1sum, const double* __restrict__ s1sq,
    const float4* __restrict__ Wb4,
    float* __restrict__ z,
    double* __restrict__ osum, double* __restrict__ osq) {
    __shared__ __align__(16) float h[20][64];
    __shared__ float mean[64], istd[64];
    __shared__ int jj[16][20];
    __shared__ float red[256];
    const int tid = threadIdx.x;     // 256
    const int n0 = blockIdx.x * 16;
    const int o = tid & 63, kh = tid >> 6;

    u64 w2[32];
    #pragma unroll
    for (int cq = 0; cq < 16; cq++) {
        float4 w = Wb4[o * 16 + cq];
        w2[cq * 2]     = pk2(w.x, w.y);
        w2[cq * 2 + 1] = pk2(w.z, w.w);
    }
    if (tid < 64) {
        double m = s1sum[tid] / (double)MPAIR;
        double v = s1sq[tid] / (double)MPAIR - m * m;
        mean[tid] = (float)m;
        istd[tid] = (float)(1.0 / sqrt(v + EPSV));
    }
    for (int e = tid; e < 320; e += 256) {
        int p = e / 20, k = e - p * 20;
        jj[p][k] = idx[(n0 + p) * KNN_TOT + k * stride];
    }
    __syncthreads();

    float sA = 0.f, sQ = 0.f;
    for (int p = 0; p < 16; p++) {
        int n = n0 + p;
        for (int e = tid; e < 320; e += 256) {
            int k = e >> 4, cq = e & 15;
            float4 a = A4[jj[p][k] * 16 + cq];
            float4 b = B4[n * 16 + cq];
            int c0 = cq * 4;
            float4 r;
            r.x = lrelu((a.x + b.x - mean[c0 + 0]) * istd[c0 + 0]);
            r.y = lrelu((a.y + b.y - mean[c0 + 1]) * istd[c0 + 1]);
            r.z = lrelu((a.z + b.z - mean[c0 + 2]) * istd[c0 + 2]);
            r.w = lrelu((a.w + b.w - mean[c0 + 3]) * istd[c0 + 3]);
            *(float4*)&h[k][c0] = r;
        }
        __syncthreads();

        u64 acc[10];
        #pragma unroll
        for (int q = 0; q < 10; q++) acc[q] = 0ull;
        #pragma unroll
        for (int cq = 0; cq < 16; cq++) {
            #pragma unroll
            for (int q = 0; q < 5; q++) {
                const u64* hv = (const u64*)&h[kh * 5 + q][cq * 4];
                ffma2(acc[q * 2],     w2[cq * 2],     hv[0]);
                ffma2(acc[q * 2 + 1], w2[cq * 2 + 1], hv[1]);
            }
        }
        float ymax = -INFINITY;
        #pragma unroll
        for (int q = 0; q < 5; q++) {
            float y = (f2lo(acc[q * 2]) + f2hi(acc[q * 2])) +
                      (f2lo(acc[q * 2 + 1]) + f2hi(acc[q * 2 + 1]));
            sA += y;
            sQ = fmaf(y, y, sQ);
            ymax = fmaxf(ymax, y);
        }
        red[tid] = ymax;
        __syncthreads();
        if (tid < 64)
            z[n * 64 + tid] = fmaxf(fmaxf(red[tid], red[tid + 64]),
                                    fmaxf(red[tid + 128], red[tid + 192]));
        __syncthreads();
    }
    red[tid] = sA;
    __syncthreads();
    if (tid < 64)
        atomicAdd(&osum[tid], (double)(red[tid] + red[tid + 64] + red[tid + 128] + red[tid + 192]));
    __syncthreads();
    red[tid] = sQ;
    __syncthreads();
    if (tid < 64)
        atomicAdd(&osq[tid], (double)(red[tid] + red[tid + 64] + red[tid + 128] + red[tid + 192]));
}

// ---------------- edge-block finalize ----------------
__global__ void edgefin_kernel(const float* __restrict__ z,
                               const double* __restrict__ s, const double* __restrict__ q,
                               const float* __restrict__ res,
                               float* __restrict__ xo) {
    __shared__ float mean[64], istd[64];
    int tid = threadIdx.x;   // 256
    if (tid < 64) {
        double m = s[tid] / (double)MPAIR;
        double v = q[tid] / (double)MPAIR - m * m;
        mean[tid] = (float)m;
        istd[tid] = (float)(1.0 / sqrt(v + EPSV));
    }
    __syncthreads();
    int t0 = blockIdx.x * 256 + tid;
    int c = t0 & 63;
    float v = lrelu((z[t0] - mean[c]) * istd[c]);
    if (res) v += res[t0];
    xo[t0] = v;
}

// ---------------- g stats: W9 in smem, 4-pt ILP, f32x2 ----------------
__global__ void __launch_bounds__(128) gstat_kernel(
    const float* __restrict__ x1, const float* __restrict__ x2,
    const float* __restrict__ x3, const float* __restrict__ x4,
    const float* __restrict__ W9,
    double* __restrict__ gsum, double* __restrict__ gsq, float* __restrict__ gmax) {
    extern __shared__ float ws[];               // 128 * 258
    __shared__ __align__(16) float f[4 * 256];
    const int tid = threadIdx.x;  // 128
    for (int e = tid; e < 128 * 256; e += 128) {
        int o = e >> 8, c = e & 255;
        ws[o * 258 + c] = W9[e];
    }
    __syncthreads();
    float ls = 0.f, lq = 0.f, lm = -INFINITY;
    const int n0 = blockIdx.x * 64;
    const u64* wrow = (const u64*)(ws + tid * 258);
    for (int it = 0; it < 16; it++) {
        int nb = n0 + it * 4;
        for (int e = tid; e < 1024; e += 128) {
            int p = e >> 8, c = e & 255;
            const float* src = (c < 64) ? x1 : (c < 128) ? x2 : (c < 192) ? x3 : x4;
            f[e] = src[(nb + p) * 64 + (c & 63)];
        }
        __syncthreads();
        u64 acc[4] = {0ull, 0ull, 0ull, 0ull};
        const u64* f2 = (const u64*)f;
        #pragma unroll 8
        for (int c2 = 0; c2 < 128; c2++) {
            u64 w = wrow[c2];
            #pragma unroll
            for (int q = 0; q < 4; q++) ffma2(acc[q], w, f2[q * 128 + c2]);
        }
        #pragma unroll
        for (int q = 0; q < 4; q++) {
            float y = f2lo(acc[q]) + f2hi(acc[q]);
            ls += y;
            lq = fmaf(y, y, lq);
            lm = fmaxf(lm, y);
        }
        __syncthreads();
    }
    atomicAdd(&gsum[tid], (double)ls);
    atomicAdd(&gsq[tid], (double)lq);
    atomicMaxFloat(&gmax[tid], lm);
}

// ---------------- g finalize + b10 ----------------
__global__ void gfinal_kernel(const double* __restrict__ gsum, const double* __restrict__ gsq,
                              const float* __restrict__ gmax,
                              const float* __restrict__ W10, float* __restrict__ b10) {
    __shared__ float gg[128];
    int tid = threadIdx.x;   // 128
    double m = gsum[tid] / 8192.0;
    double v = gsq[tid] / 8192.0 - m * m;
    float u = (gmax[tid] - (float)m) * (float)(1.0 / sqrt(v + EPSV));
    gg[tid] = lrelu(u);
    __syncthreads();
    float acc = 0.f;
    #pragma unroll 4
    for (int c = 0; c < 128; c++) acc = fmaf(W10[tid * 192 + c], gg[c], acc);
    b10[tid] = acc;
}

// ---------------- generic 1d block: W in smem, f32x2, 32 pts/block ----------------
__global__ void __launch_bounds__(256) mm1d_kernel(
    int C1, int woff1, const double* __restrict__ s1, const double* __restrict__ q1,
    const float* __restrict__ in1,
    int C2, int woff2, const float* __restrict__ in2,
    int O, int rowlen, const float* __restrict__ W, const float* __restrict__ bias,
    float* __restrict__ out,
    double* __restrict__ osum, double* __restrict__ osq) {
    extern __shared__ float ws[];       // O * CP, CP = CT+2 (even)
    __shared__ __align__(16) float f[16 * 192];
    __shared__ float mean[128], istd[128];
    const int tid = threadIdx.x;   // 256
    const int CT = C1 + C2, CP = CT + 2;

    for (int e = tid; e < O * CT; e += 256) {
        int oo = e / CT, cc = e - oo * CT;
        int col = (cc < C1) ? (woff1 + cc) : (woff2 + cc - C1);
        ws[oo * CP + cc] = W[oo * rowlen + col];
    }
    if (s1 && tid < C1) {
        double m = s1[tid] / 8192.0;
        double v = q1[tid] / 8192.0 - m * m;
        mean[tid] = (float)m;
        istd[tid] = (float)(1.0 / sqrt(v + EPSV));
    }
    __syncthreads();

    const int reps = 256 / O;            // 2 (O=128) or 4 (O=64)
    const int o = tid & (O - 1);
    const int rep = tid / O;
    const int PG = 4 * reps;             // 8 or 16
    const int n0 = blockIdx.x * 32;
    const float binit = bias ? bias[o] : 0.f;
    float ls = 0.f, lq = 0.f;

    for (int it = 0; it < 32 / PG; it++) {
        int nb = n0 + it * PG;
        for (int e = tid; e < PG * CT; e += 256) {
            int p = e / CT, c = e - p * CT;
            float v;
            if (c < C1) {
                v = in1[(nb + p) * C1 + c];
                if (s1) v = lrelu((v - mean[c]) * istd[c]);
            } else {
                v = in2[(nb + p) * C2 + (c - C1)];
            }
            f[e] = v;
        }
        __syncthreads();
        u64 acc[4];
        #pragma unroll
        for (int q = 0; q < 4; q++) acc[q] = (u64)__float_as_uint(binit);
        const int pb = rep * 4;
        const float* wr = ws + o * CP;
        for (int c2 = 0; c2 < CT / 2; c2++) {
            u64 w = *(const u64*)(wr + 2 * c2);
            #pragma unroll
            for (int q = 0; q < 4; q++)
                ffma2(acc[q], w, *(const u64*)&f[(pb + q) * CT + 2 * c2]);
        }
        #pragma unroll
        for (int q = 0; q < 4; q++) {
            float y = f2lo(acc[q]) + f2hi(acc[q]);
            out[(nb + pb + q) * O + o] = y;
            ls += y;
            lq = fmaf(y, y, lq);
        }
        __syncthreads();
    }
    atomicAdd(&osum[o], (double)ls);
    atomicAdd(&osq[o], (double)lq);
}

// ---------------- per-group means of normalized t1 ----------------
__global__ void gmean_kernel(const float* __restrict__ t1,
                             const double* __restrict__ s, const double* __restrict__ q,
                             float* __restrict__ Mo) {
    __shared__ float mean[64], istd[64];
    __shared__ float r[256];
    int tid = threadIdx.x;   // 256
    int g = blockIdx.x;
    if (tid < 64) {
        double m = s[tid] / 8192.0;
        double v = q[tid] / 8192.0 - m * m;
        mean[tid] = (float)m;
        istd[tid] = (float)(1.0 / sqrt(v + EPSV));
    }
    __syncthreads();
    int c = tid & 63, a = tid >> 6;
    float acc = 0.f;
    for (int nn = a; nn < 1024; nn += 4) {
        int n = g * 1024 + nn;
        acc += lrelu((t1[n * 64 + c] - mean[c]) * istd[c]);
    }
    r[tid] = acc;
    __syncthreads();
    if (tid < 64)
        Mo[g * 64 + tid] = (r[tid] + r[tid + 64] + r[tid + 128] + r[tid + 192]) * (1.f / 1024.f);
}

// ---------------- final out = Wr @ M^T ----------------
__global__ void out_kernel(const float* __restrict__ Wr, const float* __restrict__ Mo,
                           float* __restrict__ out) {
    int tid = threadIdx.x;   // 1024
    int t = tid >> 7, cd = tid & 127;
    float acc = 0.f;
    #pragma unroll 4
    for (int c = 0; c < 64; c++) acc = fmaf(Wr[cd * 64 + c], Mo[t * 64 + c], acc);
    out[t * 128 + cd] = acc;
}

// ---------------- host ----------------
extern "C" void kernel_launch(void* const* d_in, const int* in_sizes, int n_in,
                              void* d_out, int out_size) {
    const float* x = (const float*)d_in[0];
    int base = 2;
    if (n_in >= 3 && in_sizes[2] == 1) base = 3;
    const float* W[14];
    for (int i = 0; i < 14; i++) W[i] = (const float*)d_in[base + i];

    Scratch* S = nullptr;
    cudaGetSymbolAddress((void**)&S, g_s);
    float* out = (float*)d_out;

    double* SUM = S->sum;
    double* SQ  = S->sq;

    cudaFuncSetAttribute(gstat_kernel, cudaFuncAttributeMaxDynamicSharedMemorySize, 128 * 258 * 4);
    cudaFuncSetAttribute(mm1d_kernel,  cudaFuncAttributeMaxDynamicSharedMemorySize, 128 * 194 * 4);

    zero_kernel<<<7, 256>>>(SUM, SQ, S->gmax);
    knn_kernel<<<NPTS, 512>>>(x, S->idx);

    const int strides[4] = {1, 2, 6, 18};
    const float* xin[4]  = {x, S->x1, S->x2, S->x3};
    const int    cins[4] = {3, 64, 64, 64};
    float*       xout[4] = {S->x1, S->x2, S->x3, S->x4};
    const float* resi[4] = {nullptr, S->x1, S->x2, S->x3};

    for (int e = 0; e < 4; e++) {
        const float* Wa = W[2 * e];
        const float* Wb = W[2 * e + 1];
        int s0 = 2 * e, s1 = 2 * e + 1;
        ab_kernel<<<NPTS / 16, 256>>>(xin[e], cins[e], Wa, S->A, S->B);
        stats1_kernel<<<NPTS / 16, 256>>>((const float4*)S->A, (const float4*)S->B,
                                          S->idx, strides[e],
                                          SUM + s0 * 128, SQ + s0 * 128);
        conv2max_kernel<<<NPTS / 16, 256>>>((const float4*)S->A, (const float4*)S->B,
                                            S->idx, strides[e],
                                            SUM + s0 * 128, SQ + s0 * 128,
                                            (const float4*)Wb,
                                            S->z, SUM + s1 * 128, SQ + s1 * 128);
        edgefin_kernel<<<NPTS * 64 / 256, 256>>>(S->z, SUM + s1 * 128, SQ + s1 * 128,
                                                 resi[e], xout[e]);
    }

    gstat_kernel<<<128, 128, 128 * 258 * 4>>>(S->x1, S->x2, S->x3, S->x4, W[8],
                                              SUM + 8 * 128, SQ + 8 * 128, S->gmax);
    gfinal_kernel<<<1, 128>>>(SUM + 8 * 128, SQ + 8 * 128, S->gmax, W[9], S->b10);

    // stage 1: t4 = W10 @ [g; x4] (g folded into bias), stats slot 9
    mm1d_kernel<<<256, 256, 128 * 66 * 4>>>(
        64, 128, nullptr, nullptr, S->x4,
        0, 0, nullptr,
        128, 192, W[9], S->b10,
        S->t4, SUM + 9 * 128, SQ + 9 * 128);
    // stage 2: t3 = W11 @ [norm(t4); x3], stats slot 10
    mm1d_kernel<<<256, 256, 128 * 194 * 4>>>(
        128, 0, SUM + 9 * 128, SQ + 9 * 128, S->t4,
        64, 128, S->x3,
        128, 192, W[10], nullptr,
        S->t3, SUM + 10 * 128, SQ + 10 * 128);
    // stage 3: t2 = W12 @ [norm(t3); x2], stats slot 11
    mm1d_kernel<<<256, 256, 64 * 194 * 4>>>(
        128, 0, SUM + 10 * 128, SQ + 10 * 128, S->t3,
        64, 128, S->x2,
        64, 192, W[11], nullptr,
        S->t2, SUM + 11 * 128, SQ + 11 * 128);
    // stage 4: t1 = W13 @ [norm(t2); x1], stats slot 12
    mm1d_kernel<<<256, 256, 64 * 130 * 4>>>(
        64, 0, SUM + 11 * 128, SQ + 11 * 128, S->t2,
        64, 64, S->x1,
        64, 128, W[12], nullptr,
        S->t1, SUM + 12 * 128, SQ + 12 * 128);

    gmean_kernel<<<NGRP, 256>>>(S->t1, SUM + 12 * 128, SQ + 12 * 128, S->M);
    out_kernel<<<1, 1024>>>(W[13], S->M, out);
}

// round 4
// speedup vs baseline: 3.9485x; 1.0070x over previous
#include <cuda_runtime.h>
#include <math.h>

#define NPTS 8192
#define GRP  1024
#define NGRP 8
#define KNN_TOT 360
#define MPAIR (NPTS * 20)
#define EPSV 1e-5

typedef unsigned long long u64;

// ---------------- scratch (static device memory; no allocation) ----------------
struct Scratch {
    int    idx[NPTS * KNN_TOT];
    float  A[NPTS * 64];
    float  B[NPTS * 64];
    float  z[NPTS * 64];
    float  x1[NPTS * 64];
    float  x2[NPTS * 64];
    float  x3[NPTS * 64];
    float  x4[NPTS * 64];
    float  t4[NPTS * 128];
    float  t3[NPTS * 128];
    float  t2[NPTS * 64];
    float  t1[NPTS * 64];
    float  M[NGRP * 64];
    float  b10[128];
    float  gmax[128];
    double sum[13 * 128];
    double sq[13 * 128];
};
__device__ Scratch g_s;

// ---------------- helpers ----------------
__device__ __forceinline__ float lrelu(float v) { return v >= 0.f ? v : 0.2f * v; }

__device__ __forceinline__ void ffma2(u64 &d, u64 a, u64 b) {
    asm("fma.rn.f32x2 %0, %1, %2, %0;" : "+l"(d) : "l"(a), "l"(b));
}
__device__ __forceinline__ u64 pk2(float x, float y) {
    return (u64)__float_as_uint(x) | ((u64)__float_as_uint(y) << 32);
}
__device__ __forceinline__ float f2lo(u64 v) { return __uint_as_float((unsigned)v); }
__device__ __forceinline__ float f2hi(u64 v) { return __uint_as_float((unsigned)(v >> 32)); }

__device__ __forceinline__ u64 umin64(u64 a, u64 b) { return a < b ? a : b; }
__device__ __forceinline__ u64 umax64(u64 a, u64 b) { return a > b ? a : b; }

__device__ __forceinline__ void atomicMaxFloat(float* addr, float val) {
    int* ai = (int*)addr;
    int old = *ai;
    while (__int_as_float(old) < val) {
        int assumed = old;
        old = atomicCAS(ai, assumed, __float_as_int(val));
        if (old == assumed) break;
    }
}

// ---------------- zero stats ----------------
__global__ void zero_kernel(double* sum, double* sq, float* gmax) {
    int t = blockIdx.x * blockDim.x + threadIdx.x;
    if (t < 13 * 128) { sum[t] = 0.0; sq[t] = 0.0; }
    if (t < 128) gmax[t] = -INFINITY;
}

// ---------------- kNN: 8 elems/thread register/shuffle bitonic ----------------
// 512 threads = 4 points x 128 threads. 27 register passes, 25 shuffle passes,
// 3 smem passes (strides 256, 256, 512). Slot e = r*8+q; values carry source idx.
#define KNN_REGPASS(S)                                                          \
    {                                                                           \
        _Pragma("unroll")                                                       \
        for (int q = 0; q < 8; q++) {                                           \
            if (!(q & (S))) {                                                   \
                bool dirq = (((r * 8 + q) & size) != 0);                        \
                u64 a = v[q], b = v[q | (S)];                                   \
                u64 lo = umin64(a, b), hi = umax64(a, b);                       \
                v[q]       = dirq ? hi : lo;                                    \
                v[q | (S)] = dirq ? lo : hi;                                    \
            }                                                                   \
        }                                                                       \
    }

__global__ void __launch_bounds__(512) knn_kernel(const float* __restrict__ x,
                                                  int* __restrict__ idxo) {
    __shared__ u64 buf[512 * 9];             // 36 KB; coords aliased at start
    float* sc = (float*)buf;                 // sx[1024] sy[1024] sz[1024]
    const int tid = threadIdx.x;
    const int i0 = blockIdx.x * 4;
    const int base = i0 & ~(GRP - 1);
    const int pt = tid >> 7, r = tid & 127;

    for (int t = tid; t < 3072; t += 512) {
        float val = x[base * 3 + t];
        int row = t / 3, col = t - row * 3;
        sc[col * 1024 + row] = val;
    }
    __syncthreads();

    const int li = (i0 & (GRP - 1)) + pt;
    const float qx = sc[li], qy = sc[1024 + li], qz = sc[2048 + li];
    const float sqi = qx * qx + qy * qy + qz * qz;

    u64 v[8];
    #pragma unroll
    for (int q = 0; q < 8; q++) {
        int j = q * 128 + r;
        float ax = sc[j], ay = sc[1024 + j], az = sc[2048 + j];
        float d = sqi + (ax * ax + ay * ay + az * az)
                - 2.f * (qx * ax + qy * ay + qz * az);
        if (j == li) d = INFINITY;
        unsigned ub = __float_as_uint(d);
        ub ^= (ub & 0x80000000u) ? 0xFFFFFFFFu : 0x80000000u;
        v[q] = ((u64)ub << 32) | (unsigned)j;
    }

    #pragma unroll 1
    for (int size = 2; size <= GRP; size <<= 1) {
        #pragma unroll 1
        for (int s = size >> 1; s >= 8; s >>= 1) {
            const bool dir = (r & (size >> 3)) != 0;   // size >= 16 here
            const int m = s >> 3;
            const bool keepMin = ((r & m) == 0) != dir;
            if (s <= 128) {
                #pragma unroll
                for (int q = 0; q < 8; q++) {
                    u64 o = __shfl_xor_sync(0xFFFFFFFFu, v[q], m);
                    v[q] = keepMin ? umin64(v[q], o) : umax64(v[q], o);
                }
            } else {
                __syncthreads();
                #pragma unroll
                for (int q = 0; q < 8; q++) buf[tid * 9 + q] = v[q];
                __syncthreads();
                const int ptid = tid ^ m;   // m in {32, 64} stays inside point group
                #pragma unroll
                for (int q = 0; q < 8; q++) {
                    u64 o = buf[ptid * 9 + q];
                    v[q] = keepMin ? umin64(v[q], o) : umax64(v[q], o);
                }
            }
        }
        if (size > 4) KNN_REGPASS(4);
        if (size > 2) KNN_REGPASS(2);
        KNN_REGPASS(1);
    }

    if (r < KNN_TOT / 8) {   // r < 45: slots 0..359
        const int i = i0 + pt;
        #pragma unroll
        for (int q = 0; q < 8; q++)
            idxo[i * KNN_TOT + r * 8 + q] = base + (int)(v[q] & 0xFFFFFFFFu);
    }
}

// ---------------- A/B precompute edge 1 (raw x, Cin=3) ----------------
__global__ void __launch_bounds__(256) ab_kernel(const float* __restrict__ X,
                                                 const float* __restrict__ W,
                                                 float* __restrict__ A, float* __restrict__ B) {
    __shared__ float a_s[3 * 64];
    __shared__ float d_s[3 * 64];
    __shared__ float xs[16 * 64];
    const int tid = threadIdx.x;
    const int n0 = blockIdx.x * 16;

    if (tid < 3 * 64) {
        int c = tid >> 6, o = tid & 63;
        float wn = W[o * 6 + c];
        float wc = W[o * 6 + 3 + c];
        a_s[c * 64 + o] = wn;
        d_s[c * 64 + o] = wc - wn;
    }
    for (int e = tid; e < 16 * 3; e += 256) {
        int p = e / 3, c = e - p * 3;
        xs[p * 64 + c] = X[(n0 + p) * 3 + c];
    }
    __syncthreads();

    const int o = tid & 63, pg = tid >> 6;
    float aa[4] = {0.f, 0.f, 0.f, 0.f}, bb[4] = {0.f, 0.f, 0.f, 0.f};
    #pragma unroll
    for (int c = 0; c < 3; c++) {
        float wn = a_s[c * 64 + o], wd = d_s[c * 64 + o];
        #pragma unroll
        for (int q = 0; q < 4; q++) {
            float xv = xs[(pg * 4 + q) * 64 + c];
            aa[q] = fmaf(wn, xv, aa[q]);
            bb[q] = fmaf(wd, xv, bb[q]);
        }
    }
    #pragma unroll
    for (int q = 0; q < 4; q++) {
        int n = n0 + pg * 4 + q;
        A[n * 64 + o] = aa[q];
        B[n * 64 + o] = bb[q];
    }
}

// ---------------- fused: finalize previous edge + A/B for this edge ----------------
// x = lrelu((z - m)*istd) + res   (written to xout), then A/B = decomposed conv1(x).
__global__ void __launch_bounds__(256) abfuse_kernel(
    const float* __restrict__ z,
    const double* __restrict__ s, const double* __restrict__ q_,
    const float* __restrict__ res,
    float* __restrict__ xout,
    const float* __restrict__ W,
    float* __restrict__ A, float* __restrict__ B) {
    __shared__ float a_s[64 * 64];
    __shared__ float d_s[64 * 64];
    __shared__ float xs[16 * 64];
    __shared__ float mean[64], istd[64];
    const int tid = threadIdx.x;
    const int n0 = blockIdx.x * 16;

    for (int e = tid; e < 64 * 64; e += 256) {
        int c = e >> 6, o = e & 63;
        float wn = W[o * 128 + c];
        float wc = W[o * 128 + 64 + c];
        a_s[c * 64 + o] = wn;
        d_s[c * 64 + o] = wc - wn;
    }
    if (tid < 64) {
        double m = s[tid] / (double)MPAIR;
        double vv = q_[tid] / (double)MPAIR - m * m;
        mean[tid] = (float)m;
        istd[tid] = (float)(1.0 / sqrt(vv + EPSV));
    }
    __syncthreads();

    for (int e = tid; e < 16 * 64; e += 256) {
        int p = e >> 6, c = e & 63;
        int n = n0 + p;
        float val = lrelu((z[n * 64 + c] - mean[c]) * istd[c]);
        if (res) val += res[n * 64 + c];
        xs[e] = val;
        xout[n * 64 + c] = val;
    }
    __syncthreads();

    const int o = tid & 63, pg = tid >> 6;
    float aa[4] = {0.f, 0.f, 0.f, 0.f}, bb[4] = {0.f, 0.f, 0.f, 0.f};
    for (int c = 0; c < 64; c++) {
        float wn = a_s[c * 64 + o], wd = d_s[c * 64 + o];
        #pragma unroll
        for (int q = 0; q < 4; q++) {
            float xv = xs[(pg * 4 + q) * 64 + c];
            aa[q] = fmaf(wn, xv, aa[q]);
            bb[q] = fmaf(wd, xv, bb[q]);
        }
    }
    #pragma unroll
    for (int q = 0; q < 4; q++) {
        int n = n0 + pg * 4 + q;
        A[n * 64 + o] = aa[q];
        B[n * 64 + o] = bb[q];
    }
}

// ---------------- y1 statistics (8 points/block, 128 threads) ----------------
__global__ void __launch_bounds__(128) stats1_kernel(const float4* __restrict__ A4,
                                                     const float4* __restrict__ B4,
                                                     const int* __restrict__ idx, int stride,
                                                     double* __restrict__ gsum,
                                                     double* __restrict__ gsq) {
    __shared__ int jj[8][20];
    __shared__ float r1[64], r2[64];
    const int tid = threadIdx.x;   // 128
    const int n0 = blockIdx.x * 8;
    if (tid < 64) { r1[tid] = 0.f; r2[tid] = 0.f; }
    for (int e = tid; e < 160; e += 128) {
        int p = e / 20, k = e - p * 20;
        jj[p][k] = idx[(n0 + p) * KNN_TOT + k * stride];
    }
    __syncthreads();
    const int p = tid >> 4, c4 = tid & 15;
    float4 bv = B4[(n0 + p) * 16 + c4];
    float4 s1 = {0.f, 0.f, 0.f, 0.f}, s2 = {0.f, 0.f, 0.f, 0.f};
    #pragma unroll
    for (int k = 0; k < 20; k++) {
        float4 a = A4[jj[p][k] * 16 + c4];
        float hx = a.x + bv.x, hy = a.y + bv.y, hz = a.z + bv.z, hw = a.w + bv.w;
        s1.x += hx; s1.y += hy; s1.z += hz; s1.w += hw;
        s2.x = fmaf(hx, hx, s2.x); s2.y = fmaf(hy, hy, s2.y);
        s2.z = fmaf(hz, hz, s2.z); s2.w = fmaf(hw, hw, s2.w);
    }
    atomicAdd(&r1[c4 * 4 + 0], s1.x); atomicAdd(&r1[c4 * 4 + 1], s1.y);
    atomicAdd(&r1[c4 * 4 + 2], s1.z); atomicAdd(&r1[c4 * 4 + 3], s1.w);
    atomicAdd(&r2[c4 * 4 + 0], s2.x); atomicAdd(&r2[c4 * 4 + 1], s2.y);
    atomicAdd(&r2[c4 * 4 + 2], s2.z); atomicAdd(&r2[c4 * 4 + 3], s2.w);
    __syncthreads();
    if (tid < 64) {
        atomicAdd(&gsum[tid], (double)r1[tid]);
        atomicAdd(&gsq[tid], (double)r2[tid]);
    }
}

// ---------------- conv2 + max-over-k + y2 stats (8 pts/block, f32x2) ----------------
__global__ void __launch_bounds__(256) conv2max_kernel(
    const float4* __restrict__ A4, const float4* __restrict__ B4,
    const int* __restrict__ idx, int stride,
    const double* __restrict__ s1sum, const double* __restrict__ s1sq,
    const float4* __restrict__ Wb4,
    float* __restrict__ z,
    double* __restrict__ osum, double* __restrict__ osq) {
    __shared__ __align__(16) float h[20][64];
    __shared__ float mean[64], istd[64];
    __shared__ int jj[8][20];
    __shared__ float red[256];
    const int tid = threadIdx.x;     // 256
    const int n0 = blockIdx.x * 8;
    const int o = tid & 63, kh = tid >> 6;

    u64 w2[32];
    #pragma unroll
    for (int cq = 0; cq < 16; cq++) {
        float4 w = Wb4[o * 16 + cq];
        w2[cq * 2]     = pk2(w.x, w.y);
        w2[cq * 2 + 1] = pk2(w.z, w.w);
    }
    if (tid < 64) {
        double m = s1sum[tid] / (double)MPAIR;
        double v = s1sq[tid] / (double)MPAIR - m * m;
        mean[tid] = (float)m;
        istd[tid] = (float)(1.0 / sqrt(v + EPSV));
    }
    for (int e = tid; e < 160; e += 256) {
        int p = e / 20, k = e - p * 20;
        jj[p][k] = idx[(n0 + p) * KNN_TOT + k * stride];
    }
    __syncthreads();

    float sA = 0.f, sQ = 0.f;
    for (int p = 0; p < 8; p++) {
        int n = n0 + p;
        for (int e = tid; e < 320; e += 256) {
            int k = e >> 4, cq = e & 15;
            float4 a = A4[jj[p][k] * 16 + cq];
            float4 b = B4[n * 16 + cq];
            int c0 = cq * 4;
            float4 r;
            r.x = lrelu((a.x + b.x - mean[c0 + 0]) * istd[c0 + 0]);
            r.y = lrelu((a.y + b.y - mean[c0 + 1]) * istd[c0 + 1]);
            r.z = lrelu((a.z + b.z - mean[c0 + 2]) * istd[c0 + 2]);
            r.w = lrelu((a.w + b.w - mean[c0 + 3]) * istd[c0 + 3]);
            *(float4*)&h[k][c0] = r;
        }
        __syncthreads();

        u64 acc[10];
        #pragma unroll
        for (int q = 0; q < 10; q++) acc[q] = 0ull;
        #pragma unroll
        for (int cq = 0; cq < 16; cq++) {
            #pragma unroll
            for (int q = 0; q < 5; q++) {
                const u64* hv = (const u64*)&h[kh * 5 + q][cq * 4];
                ffma2(acc[q * 2],     w2[cq * 2],     hv[0]);
                ffma2(acc[q * 2 + 1], w2[cq * 2 + 1], hv[1]);
            }
        }
        float ymax = -INFINITY;
        #pragma unroll
        for (int q = 0; q < 5; q++) {
            float y = (f2lo(acc[q * 2]) + f2hi(acc[q * 2])) +
                      (f2lo(acc[q * 2 + 1]) + f2hi(acc[q * 2 + 1]));
            sA += y;
            sQ = fmaf(y, y, sQ);
            ymax = fmaxf(ymax, y);
        }
        red[tid] = ymax;
        __syncthreads();
        if (tid < 64)
            z[n * 64 + tid] = fmaxf(fmaxf(red[tid], red[tid + 64]),
                                    fmaxf(red[tid + 128], red[tid + 192]));
        __syncthreads();
    }
    red[tid] = sA;
    __syncthreads();
    if (tid < 64)
        atomicAdd(&osum[tid], (double)(red[tid] + red[tid + 64] + red[tid + 128] + red[tid + 192]));
    __syncthreads();
    red[tid] = sQ;
    __syncthreads();
    if (tid < 64)
        atomicAdd(&osq[tid], (double)(red[tid] + red[tid + 64] + red[tid + 128] + red[tid + 192]));
}

// ---------------- g stats + fused edge-4 finalize ----------------
// x4 = lrelu((z - m7)*i7) + x3 (written out), u = W9 @ [x1;x2;x3;x4], stats+max of u.
__global__ void __launch_bounds__(128) gstat_kernel(
    const float* __restrict__ x1, const float* __restrict__ x2,
    const float* __restrict__ x3,
    const float* __restrict__ z,
    const double* __restrict__ s7, const double* __restrict__ q7,
    float* __restrict__ x4,
    const float* __restrict__ W9,
    double* __restrict__ gsum, double* __restrict__ gsq, float* __restrict__ gmax) {
    extern __shared__ float ws[];               // 128 * 258
    __shared__ __align__(16) float f[4 * 256];
    __shared__ float m4[64], i4[64];
    const int tid = threadIdx.x;  // 128
    for (int e = tid; e < 128 * 256; e += 128) {
        int o = e >> 8, c = e & 255;
        ws[o * 258 + c] = W9[e];
    }
    if (tid < 64) {
        double m = s7[tid] / (double)MPAIR;
        double v = q7[tid] / (double)MPAIR - m * m;
        m4[tid] = (float)m;
        i4[tid] = (float)(1.0 / sqrt(v + EPSV));
    }
    __syncthreads();
    float ls = 0.f, lq = 0.f, lm = -INFINITY;
    const int n0 = blockIdx.x * 64;
    const u64* wrow = (const u64*)(ws + tid * 258);
    for (int it = 0; it < 16; it++) {
        int nb = n0 + it * 4;
        for (int e = tid; e < 1024; e += 128) {
            int p = e >> 8, c = e & 255;
            int n = nb + p, cc = c & 63;
            float val;
            if (c < 64)       val = x1[n * 64 + cc];
            else if (c < 128) val = x2[n * 64 + cc];
            else if (c < 192) val = x3[n * 64 + cc];
            else {
                val = lrelu((z[n * 64 + cc] - m4[cc]) * i4[cc]) + x3[n * 64 + cc];
                x4[n * 64 + cc] = val;
            }
            f[e] = val;
        }
        __syncthreads();
        u64 acc[4] = {0ull, 0ull, 0ull, 0ull};
        const u64* f2 = (const u64*)f;
        #pragma unroll 8
        for (int c2 = 0; c2 < 128; c2++) {
            u64 w = wrow[c2];
            #pragma unroll
            for (int q = 0; q < 4; q++) ffma2(acc[q], w, f2[q * 128 + c2]);
        }
        #pragma unroll
        for (int q = 0; q < 4; q++) {
            float y = f2lo(acc[q]) + f2hi(acc[q]);
            ls += y;
            lq = fmaf(y, y, lq);
            lm = fmaxf(lm, y);
        }
        __syncthreads();
    }
    atomicAdd(&gsum[tid], (double)ls);
    atomicAdd(&gsq[tid], (double)lq);
    atomicMaxFloat(&gmax[tid], lm);
}

// ---------------- g finalize + b10 ----------------
__global__ void gfinal_kernel(const double* __restrict__ gsum, const double* __restrict__ gsq,
                              const float* __restrict__ gmax,
                              const float* __restrict__ W10, float* __restrict__ b10) {
    __shared__ float gg[128];
    int tid = threadIdx.x;   // 128
    double m = gsum[tid] / 8192.0;
    double v = gsq[tid] / 8192.0 - m * m;
    float u = (gmax[tid] - (float)m) * (float)(1.0 / sqrt(v + EPSV));
    gg[tid] = lrelu(u);
    __syncthreads();
    float acc = 0.f;
    #pragma unroll 4
    for (int c = 0; c < 128; c++) acc = fmaf(W10[tid * 192 + c], gg[c], acc);
    b10[tid] = acc;
}

// ---------------- generic 1d block: W in smem, f32x2, 32 pts/block ----------------
__global__ void __launch_bounds__(256) mm1d_kernel(
    int C1, int woff1, const double* __restrict__ s1, const double* __restrict__ q1,
    const float* __restrict__ in1,
    int C2, int woff2, const float* __restrict__ in2,
    int O, int rowlen, const float* __restrict__ W, const float* __restrict__ bias,
    float* __restrict__ out,
    double* __restrict__ osum, double* __restrict__ osq) {
    extern __shared__ float ws[];       // O * CP, CP = CT+2 (even)
    __shared__ __align__(16) float f[16 * 192];
    __shared__ float mean[128], istd[128];
    const int tid = threadIdx.x;   // 256
    const int CT = C1 + C2, CP = CT + 2;

    for (int e = tid; e < O * CT; e += 256) {
        int oo = e / CT, cc = e - oo * CT;
        int col = (cc < C1) ? (woff1 + cc) : (woff2 + cc - C1);
        ws[oo * CP + cc] = W[oo * rowlen + col];
    }
    if (s1 && tid < C1) {
        double m = s1[tid] / 8192.0;
        double v = q1[tid] / 8192.0 - m * m;
        mean[tid] = (float)m;
        istd[tid] = (float)(1.0 / sqrt(v + EPSV));
    }
    __syncthreads();

    const int reps = 256 / O;
    const int o = tid & (O - 1);
    const int rep = tid / O;
    const int PG = 4 * reps;
    const int n0 = blockIdx.x * 32;
    const float binit = bias ? bias[o] : 0.f;
    float ls = 0.f, lq = 0.f;

    for (int it = 0; it < 32 / PG; it++) {
        int nb = n0 + it * PG;
        for (int e = tid; e < PG * CT; e += 256) {
            int p = e / CT, c = e - p * CT;
            float v;
            if (c < C1) {
                v = in1[(nb + p) * C1 + c];
                if (s1) v = lrelu((v - mean[c]) * istd[c]);
            } else {
                v = in2[(nb + p) * C2 + (c - C1)];
            }
            f[e] = v;
        }
        __syncthreads();
        u64 acc[4];
        #pragma unroll
        for (int q = 0; q < 4; q++) acc[q] = (u64)__float_as_uint(binit);
        const int pb = rep * 4;
        const float* wr = ws + o * CP;
        for (int c2 = 0; c2 < CT / 2; c2++) {
            u64 w = *(const u64*)(wr + 2 * c2);
            #pragma unroll
            for (int q = 0; q < 4; q++)
                ffma2(acc[q], w, *(const u64*)&f[(pb + q) * CT + 2 * c2]);
        }
        #pragma unroll
        for (int q = 0; q < 4; q++) {
            float y = f2lo(acc[q]) + f2hi(acc[q]);
            out[(nb + pb + q) * O + o] = y;
            ls += y;
            lq = fmaf(y, y, lq);
        }
        __syncthreads();
    }
    atomicAdd(&osum[o], (double)ls);
    atomicAdd(&osq[o], (double)lq);
}

// ---------------- per-group means of normalized t1 ----------------
__global__ void gmean_kernel(const float* __restrict__ t1,
                             const double* __restrict__ s, const double* __restrict__ q,
                             float* __restrict__ Mo) {
    __shared__ float mean[64], istd[64];
    __shared__ float r[256];
    int tid = threadIdx.x;   // 256
    int g = blockIdx.x;
    if (tid < 64) {
        double m = s[tid] / 8192.0;
        double v = q[tid] / 8192.0 - m * m;
        mean[tid] = (float)m;
        istd[tid] = (float)(1.0 / sqrt(v + EPSV));
    }
    __syncthreads();
    int c = tid & 63, a = tid >> 6;
    float acc = 0.f;
    for (int nn = a; nn < 1024; nn += 4) {
        int n = g * 1024 + nn;
        acc += lrelu((t1[n * 64 + c] - mean[c]) * istd[c]);
    }
    r[tid] = acc;
    __syncthreads();
    if (tid < 64)
        Mo[g * 64 + tid] = (r[tid] + r[tid + 64] + r[tid + 128] + r[tid + 192]) * (1.f / 1024.f);
}

// ---------------- final out = Wr @ M^T ----------------
__global__ void out_kernel(const float* __restrict__ Wr, const float* __restrict__ Mo,
                           float* __restrict__ out) {
    int tid = threadIdx.x;   // 1024
    int t = tid >> 7, cd = tid & 127;
    float acc = 0.f;
    #pragma unroll 4
    for (int c = 0; c < 64; c++) acc = fmaf(Wr[cd * 64 + c], Mo[t * 64 + c], acc);
    out[t * 128 + cd] = acc;
}

// ---------------- host ----------------
extern "C" void kernel_launch(void* const* d_in, const int* in_sizes, int n_in,
                              void* d_out, int out_size) {
    const float* x = (const float*)d_in[0];
    int base = 2;
    if (n_in >= 3 && in_sizes[2] == 1) base = 3;
    const float* W[14];
    for (int i = 0; i < 14; i++) W[i] = (const float*)d_in[base + i];

    Scratch* S = nullptr;
    cudaGetSymbolAddress((void**)&S, g_s);
    float* out = (float*)d_out;

    double* SUM = S->sum;
    double* SQ  = S->sq;

    cudaFuncSetAttribute(gstat_kernel, cudaFuncAttributeMaxDynamicSharedMemorySize, 128 * 258 * 4);
    cudaFuncSetAttribute(mm1d_kernel,  cudaFuncAttributeMaxDynamicSharedMemorySize, 128 * 194 * 4);

    zero_kernel<<<7, 256>>>(SUM, SQ, S->gmax);
    knn_kernel<<<NPTS / 4, 512>>>(x, S->idx);

    const int strides[4] = {1, 2, 6, 18};

    // edge 1: conv1 decomposition directly from raw x
    ab_kernel<<<NPTS / 16, 256>>>(x, W[0], S->A, S->B);
    stats1_kernel<<<NPTS / 8, 128>>>((const float4*)S->A, (const float4*)S->B,
                                     S->idx, strides[0], SUM, SQ);
    conv2max_kernel<<<NPTS / 8, 256>>>((const float4*)S->A, (const float4*)S->B,
                                       S->idx, strides[0], SUM, SQ,
                                       (const float4*)W[1],
                                       S->z, SUM + 128, SQ + 128);

    // edges 2..4: abfuse finalizes the previous edge, then stats1 + conv2max
    const float* resi[3] = {nullptr, S->x1, S->x2};
    float*       xout[3] = {S->x1, S->x2, S->x3};
    for (int e = 1; e < 4; e++) {
        int sp = 2 * e - 1;            // prev conv2 stats slot
        int s0 = 2 * e, s1 = 2 * e + 1;
        abfuse_kernel<<<NPTS / 16, 256>>>(S->z, SUM + sp * 128, SQ + sp * 128,
                                          resi[e - 1], xout[e - 1],
                                          W[2 * e], S->A, S->B);
        stats1_kernel<<<NPTS / 8, 128>>>((const float4*)S->A, (const float4*)S->B,
                                         S->idx, strides[e],
                                         SUM + s0 * 128, SQ + s0 * 128);
        conv2max_kernel<<<NPTS / 8, 256>>>((const float4*)S->A, (const float4*)S->B,
                                           S->idx, strides[e],
                                           SUM + s0 * 128, SQ + s0 * 128,
                                           (const float4*)W[2 * e + 1],
                                           S->z, SUM + s1 * 128, SQ + s1 * 128);
    }

    // gstat fuses edge-4 finalize (x4 = lrelu(norm(z)) + x3)
    gstat_kernel<<<128, 128, 128 * 258 * 4>>>(S->x1, S->x2, S->x3,
                                              S->z, SUM + 7 * 128, SQ + 7 * 128, S->x4,
                                              W[8],
                                              SUM + 8 * 128, SQ + 8 * 128, S->gmax);
    gfinal_kernel<<<1, 128>>>(SUM + 8 * 128, SQ + 8 * 128, S->gmax, W[9], S->b10);

    mm1d_kernel<<<256, 256, 128 * 66 * 4>>>(
        64, 128, nullptr, nullptr, S->x4,
        0, 0, nullptr,
        128, 192, W[9], S->b10,
        S->t4, SUM + 9 * 128, SQ + 9 * 128);
    mm1d_kernel<<<256, 256, 128 * 194 * 4>>>(
        128, 0, SUM + 9 * 128, SQ + 9 * 128, S->t4,
        64, 128, S->x3,
        128, 192, W[10], nullptr,
        S->t3, SUM + 10 * 128, SQ + 10 * 128);
    mm1d_kernel<<<256, 256, 64 * 194 * 4>>>(
        128, 0, SUM + 10 * 128, SQ + 10 * 128, S->t3,
        64, 128, S->x2,
        64, 192, W[11], nullptr,
        S->t2, SUM + 11 * 128, SQ + 11 * 128);
    mm1d_kernel<<<256, 256, 64 * 130 * 4>>>(
        64, 0, SUM + 11 * 128, SQ + 11 * 128, S->t2,
        64, 64, S->x1,
        64, 128, W[12], nullptr,
        S->t1, SUM + 12 * 128, SQ + 12 * 128);

    gmean_kernel<<<NGRP, 256>>>(S->t1, SUM + 12 * 128, SQ + 12 * 128, S->M);
    out_kernel<<<1, 1024>>>(W[13], S->M, out);
}